// round 17
// baseline (speedup 1.0000x reference)
#include <cuda_runtime.h>
#include <cuda_fp16.h>
#include <math.h>
#include <cstdint>

// Problem constants
#define TQ 2048
#define BB 2
#define EE 1024
#define HH 16
#define DD 64
#define TB 4096          // TQ*BB
#define FF 3072          // 3*EE

#define QSCALE (0.125f * 1.44269504088896f)   // d^-0.5 * log2(e)  (softmax uses ex2)

// Scratch (allocation-free rule: __device__ globals) — all single fp16
__device__ __half g_qry16[(size_t)TB * EE];          // A for gemm0
__device__ __half g_wi16[(size_t)FF * EE];           // W_in
__device__ __half g_wo16[(size_t)EE * EE];           // W_out
__device__ __half g_q16[(size_t)BB * HH * TQ * DD];  // Q (pre-scaled)
__device__ __half g_k16[(size_t)BB * HH * TQ * DD];  // K
__device__ __half g_v16[(size_t)BB * HH * TQ * DD];  // V
__device__ __half g_ctx16[(size_t)TB * EE];          // A for gemm1

// ============================================================================
// helpers
// ============================================================================
__device__ __forceinline__ uint32_t smem_u32(const void* p) {
    uint32_t a;
    asm("{ .reg .u64 t; cvta.to.shared.u64 t, %1; cvt.u32.u64 %0, t; }" : "=r"(a) : "l"(p));
    return a;
}
__device__ __forceinline__ uint32_t cvt2h(float x, float y) {
    __half2 h = __floats2half2_rn(x, y);
    return *(uint32_t*)&h;
}
__device__ __forceinline__ float ex2f(float x) {
    float y;
    asm("ex2.approx.f32 %0, %1;" : "=f"(y) : "f"(x));
    return y;
}
__device__ __forceinline__ void mma_f16(float* d, const uint32_t* a, const uint32_t* b) {
    asm volatile(
        "mma.sync.aligned.m16n8k16.row.col.f32.f16.f16.f32 "
        "{%0,%1,%2,%3}, {%4,%5,%6,%7}, {%8,%9}, {%0,%1,%2,%3};"
        : "+f"(d[0]), "+f"(d[1]), "+f"(d[2]), "+f"(d[3])
        : "r"(a[0]), "r"(a[1]), "r"(a[2]), "r"(a[3]), "r"(b[0]), "r"(b[1]));
}
#define LDSM_X4(R0,R1,R2,R3,ADDR) \
    asm volatile("ldmatrix.sync.aligned.m8n8.x4.shared.b16 {%0,%1,%2,%3}, [%4];" \
        : "=r"(R0), "=r"(R1), "=r"(R2), "=r"(R3) : "r"(ADDR))
#define LDSM_X4_T(R0,R1,R2,R3,ADDR) \
    asm volatile("ldmatrix.sync.aligned.m8n8.x4.trans.shared.b16 {%0,%1,%2,%3}, [%4];" \
        : "=r"(R0), "=r"(R1), "=r"(R2), "=r"(R3) : "r"(ADDR))
#define CP16(SM, GP) \
    asm volatile("cp.async.cg.shared.global [%0], [%1], 16;" :: "r"(SM), "l"(GP) : "memory")
#define CP_COMMIT() asm volatile("cp.async.commit_group;" ::: "memory")
#define CP_WAIT(N)  asm volatile("cp.async.wait_group %0;" :: "n"(N) : "memory")
// named barrier among 128 threads (memory-fencing for participants)
#define BAR_GRP(ID) asm volatile("bar.sync %0, 128;" :: "r"(ID) : "memory")

// ============================================================================
// fp32 -> fp16 convert (elementwise, HBM-bound, one-time)
// ============================================================================
__global__ void cvt16_kernel(const float* __restrict__ src, __half* __restrict__ dst, int n4)
{
    int i = blockIdx.x * blockDim.x + threadIdx.x;
    if (i < n4) {
        float4 v = ((const float4*)src)[i];
        ((uint2*)dst)[i] = make_uint2(cvt2h(v.x, v.y), cvt2h(v.z, v.w));
    }
}

// ============================================================================
// GEMM v6 (pure fp16, single pass) — unchanged from round 14.
// 256 threads, 128x128 CTA tile, warp tile 64x32, 4-stage cp.async,
// pair-commit loop, 2 CTAs/SM.
// ============================================================================
#define GBK 32
#define GNC (EE / GBK)          // 32 chunks -> 16 pairs
#define GS_A  0
#define GS_B  8192
#define G_STAGE 16384
#define GEMM_SMEM6 (4 * G_STAGE)   // 65536

template <int MODE>
__global__ __launch_bounds__(256, 2)
void mma_gemm6(const __half* __restrict__ Ag, const __half* __restrict__ Bg,
               const float* __restrict__ bias, float* __restrict__ Cout)
{
    extern __shared__ char smem[];
    const uint32_t sb = smem_u32(smem);

    const int tid  = threadIdx.x;
    const int wid  = tid >> 5;
    const int lane = tid & 31;
    const int g    = lane >> 2;
    const int t    = lane & 3;
    const int wm   = (wid >> 2) << 6;   // 0 or 64
    const int wn   = (wid & 3) << 5;    // 0..96
    const int row0 = blockIdx.y * 128;
    const int col0 = blockIdx.x * 128;
    const int rK   = (lane & 7) + ((lane >> 4) & 1) * 8;
    const int cKb  = (lane >> 3) & 1;

    float acc[4][4][4];
#pragma unroll
    for (int i = 0; i < 4; i++)
#pragma unroll
        for (int j = 0; j < 4; j++)
#pragma unroll
            for (int k = 0; k < 4; k++) acc[i][j][k] = 0.0f;

    auto issue_nc = [&](int c) {
        uint32_t st = sb + (uint32_t)(c & 3) * G_STAGE;
#pragma unroll
        for (int p = 0; p < 2; p++) {
            int id = tid + p * 256;
            int r  = id >> 2;
            int cg = id & 3;
            uint32_t so = (uint32_t)r * 64 + (uint32_t)((cg ^ ((r >> 1) & 3)) << 4);
            size_t ka = (size_t)(row0 + r) * EE + cg * 8 + (size_t)c * GBK;
            size_t kb = (size_t)(col0 + r) * EE + cg * 8 + (size_t)c * GBK;
            CP16(st + GS_A + so, Ag + ka);
            CP16(st + GS_B + so, Bg + kb);
        }
    };
    auto issue_pair = [&](int p) {
        issue_nc(2 * p);
        issue_nc(2 * p + 1);
        CP_COMMIT();
    };

    auto compute = [&](int c) {
        uint32_t base = sb + (uint32_t)(c & 3) * G_STAGE;
#pragma unroll
        for (int ks = 0; ks < 2; ks++) {
            uint32_t ah[4][4];
#pragma unroll
            for (int ma = 0; ma < 4; ma++) {
                int row  = wm + 16 * ma + (lane & 15);
                int cgrp = ks * 2 + (lane >> 4);
                uint32_t ad = base + GS_A + row * 64 + ((cgrp ^ ((row >> 1) & 3)) << 4);
                LDSM_X4(ah[ma][0], ah[ma][1], ah[ma][2], ah[ma][3], ad);
            }
            uint32_t bh2[4][2];
#pragma unroll
            for (int jj = 0; jj < 2; jj++) {
                int row  = wn + 16 * jj + rK;
                int cgrp = ks * 2 + cKb;
                uint32_t ad = base + GS_B + row * 64 + ((cgrp ^ ((row >> 1) & 3)) << 4);
                LDSM_X4(bh2[2 * jj][0], bh2[2 * jj][1], bh2[2 * jj + 1][0], bh2[2 * jj + 1][1], ad);
            }
#pragma unroll
            for (int ma = 0; ma < 4; ma++)
#pragma unroll
                for (int na = 0; na < 4; na++) mma_f16(acc[ma][na], ah[ma], bh2[na]);
        }
    };

    issue_pair(0);
    for (int p = 0; p < GNC / 2; p++) {
        CP_WAIT(0);
        __syncthreads();
        if (p + 1 < GNC / 2) issue_pair(p + 1);
        compute(2 * p);
        compute(2 * p + 1);
    }

    // ---- epilogue ----
#pragma unroll
    for (int na = 0; na < 4; na++) {
        const int f0 = col0 + wn + 8 * na + 2 * t;
        const float b0 = bias[f0];
        const float b1 = bias[f0 + 1];
        if (MODE == 0) {
            int h     = f0 / 192;
            int rem   = f0 - 192 * h;
            int which = rem >> 6;
            int dd    = rem & 63;
            __half* dst = (which == 0) ? g_q16 : ((which == 1) ? g_k16 : g_v16);
            float mul = (which == 0) ? QSCALE : 1.0f;
#pragma unroll
            for (int ma = 0; ma < 4; ma++) {
                const float* d4 = acc[ma][na];
                int tb = row0 + wm + 16 * ma + g;
#pragma unroll
                for (int hh = 0; hh < 2; hh++) {
                    int tbx = tb + 8 * hh;
                    int tt = tbx >> 1, bb = tbx & 1;
                    size_t off = ((size_t)(bb * HH + h) * TQ + tt) * DD + dd;
                    *(uint32_t*)(dst + off) =
                        cvt2h((d4[2 * hh] + b0) * mul, (d4[2 * hh + 1] + b1) * mul);
                }
            }
        } else {
#pragma unroll
            for (int ma = 0; ma < 4; ma++) {
                const float* d4 = acc[ma][na];
                int r = row0 + wm + 16 * ma + g;
                *(float2*)(Cout + (size_t)r * EE + f0) = make_float2(d4[0] + b0, d4[1] + b1);
                *(float2*)(Cout + (size_t)(r + 8) * EE + f0) = make_float2(d4[2] + b0, d4[3] + b1);
            }
        }
    }
}

// ============================================================================
// Flash attention v6 (pure fp16, SPLIT-GROUP): the 256-thread CTA is two
// independent 128-thread groups (warps 0-3: q-rows 0-63; warps 4-7: 64-127).
// Each group owns a private 3-stage KV ring (Q overlays its stage-0 K region)
// and syncs only via its own named barrier -> groups drift freely, so one
// group's serial softmax overlaps the other's HMMA. No __syncthreads at all.
// ============================================================================
#define AG_ST 16384                // per stage: K 0..8K, V 8K..16K
#define AG_BYTES (3 * AG_ST)       // 48KB per group
#define ATTN_SMEM6 (2 * AG_BYTES)  // 96KB per CTA
#define NTILES (TQ / 64)           // 32

__global__ __launch_bounds__(256, 2)
void attn_mma6()
{
    extern __shared__ char sm[];
    const uint32_t sb = smem_u32(sm);

    const int tid  = threadIdx.x;
    const int wid  = tid >> 5;
    const int lane = tid & 31;
    const int g    = lane >> 2;
    const int t    = lane & 3;
    const int gid  = wid >> 2;          // group 0 or 1
    const int wg   = wid & 3;           // warp within group
    const int wtid = tid & 127;         // thread within group
    const int barid = 1 + gid;          // named barrier id (0 reserved)
    const uint32_t gb = sb + (uint32_t)gid * AG_BYTES;

    const int bh = blockIdx.y;
    const int b  = bh >> 4;
    const int h  = bh & 15;
    const size_t base = (size_t)bh * TQ * DD;
    const int qrow0 = blockIdx.x * 128 + gid * 64;   // this group's 64 q-rows
    const int m0 = wg * 16;

    const int rK  = (lane & 7) + ((lane >> 4) & 1) * 8;
    const int cKb = (lane >> 3) & 1;
    const int rV  = (lane & 7) + ((lane >> 3) & 1) * 8;
    const int cVb = (lane >> 4) & 1;

    // group Q copy: 64 rows x 128B = 512 x 16B chunks over 128 threads
    auto issueQ = [&]() {   // into group stage 0's K region (8KB, exact overlay)
#pragma unroll
        for (int p = 0; p < 4; p++) {
            int id = wtid + p * 128;
            int r = id >> 3, cgp = id & 7;
            uint32_t so = (uint32_t)r * 128 + ((cgp ^ (r & 7)) << 4);
            CP16(gb + so, g_q16 + base + (size_t)(qrow0 + r) * DD + cgp * 8);
        }
        CP_COMMIT();
    };
    // group KV copy: K 8KB + V 8KB per stage
    auto issueKV = [&](int st, int stage) {
        uint32_t kvb = gb + (uint32_t)stage * AG_ST;
#pragma unroll
        for (int p = 0; p < 4; p++) {
            int id = wtid + p * 128;
            int r = id >> 3, cgp = id & 7;
            uint32_t so = (uint32_t)r * 128 + ((cgp ^ (r & 7)) << 4);
            size_t go = base + (size_t)(st + r) * DD + cgp * 8;
            CP16(kvb + so,        g_k16 + go);
            CP16(kvb + 8192 + so, g_v16 + go);
        }
        CP_COMMIT();
    };

    issueQ();
    issueKV(0, 1);
    issueKV(64, 2);
    CP_WAIT(2);           // this thread's Q copies landed
    BAR_GRP(barid);       // group-wide visibility of Q before ldmatrix

    // ---- Q fragments (persistent, fp16 single) ----
    uint32_t qh[4][4];
    {
        int row = m0 + (lane & 15);     // 0..63 within group
#pragma unroll
        for (int ks = 0; ks < 4; ks++) {
            int cgrp = ks * 2 + (lane >> 4);
            uint32_t a = gb + row * 128 + ((cgrp ^ (row & 7)) << 4);
            LDSM_X4(qh[ks][0], qh[ks][1], qh[ks][2], qh[ks][3], a);
        }
    }
    BAR_GRP(barid);       // group done reading Q; stage 0 reusable

    float O[8][4];
#pragma unroll
    for (int j = 0; j < 8; j++)
#pragma unroll
        for (int k = 0; k < 4; k++) O[j][k] = 0.0f;
    float mrow0 = -1e30f, mrow1 = -1e30f, lrow0 = 0.0f, lrow1 = 0.0f;

    for (int i = 0; i < NTILES; i++) {
        if (i + 1 < NTILES) { CP_WAIT(1); } else { CP_WAIT(0); }  // tile i landed
        BAR_GRP(barid);                       // group visibility + stage-reuse guard
        if (i + 2 < NTILES) issueKV((i + 2) * 64, (i + 3) % 3);

        uint32_t kvb = gb + (uint32_t)((i + 1) % 3) * AG_ST;

        // ---- S = Q K^T (single pass) ----
        float S[8][4];
#pragma unroll
        for (int j = 0; j < 8; j++)
#pragma unroll
            for (int k = 0; k < 4; k++) S[j][k] = 0.0f;

#pragma unroll
        for (int ks = 0; ks < 4; ks++) {
            uint32_t bh_[8][2];
#pragma unroll
            for (int jj = 0; jj < 4; jj++) {
                int row  = 16 * jj + rK;
                int cgrp = ks * 2 + cKb;
                uint32_t a = kvb + row * 128 + ((cgrp ^ (row & 7)) << 4);
                LDSM_X4(bh_[2 * jj][0], bh_[2 * jj][1], bh_[2 * jj + 1][0], bh_[2 * jj + 1][1], a);
            }
#pragma unroll
            for (int j = 0; j < 8; j++) mma_f16(S[j], qh[ks], bh_[j]);
        }

        // ---- online softmax (base-2) ----
        float mx0 = -1e30f, mx1 = -1e30f;
#pragma unroll
        for (int j = 0; j < 8; j++) {
            mx0 = fmaxf(mx0, fmaxf(S[j][0], S[j][1]));
            mx1 = fmaxf(mx1, fmaxf(S[j][2], S[j][3]));
        }
        mx0 = fmaxf(mx0, __shfl_xor_sync(0xffffffffu, mx0, 1));
        mx0 = fmaxf(mx0, __shfl_xor_sync(0xffffffffu, mx0, 2));
        mx1 = fmaxf(mx1, __shfl_xor_sync(0xffffffffu, mx1, 1));
        mx1 = fmaxf(mx1, __shfl_xor_sync(0xffffffffu, mx1, 2));
        float mn0 = fmaxf(mrow0, mx0), mn1 = fmaxf(mrow1, mx1);
        float sc0 = ex2f(mrow0 - mn0), sc1 = ex2f(mrow1 - mn1);
        float s0 = 0.0f, s1 = 0.0f;
#pragma unroll
        for (int j = 0; j < 8; j++) {
            S[j][0] = ex2f(S[j][0] - mn0);
            S[j][1] = ex2f(S[j][1] - mn0);
            S[j][2] = ex2f(S[j][2] - mn1);
            S[j][3] = ex2f(S[j][3] - mn1);
            s0 += S[j][0] + S[j][1];
            s1 += S[j][2] + S[j][3];
        }
        s0 += __shfl_xor_sync(0xffffffffu, s0, 1);
        s0 += __shfl_xor_sync(0xffffffffu, s0, 2);
        s1 += __shfl_xor_sync(0xffffffffu, s1, 1);
        s1 += __shfl_xor_sync(0xffffffffu, s1, 2);
        lrow0 = lrow0 * sc0 + s0;
        lrow1 = lrow1 * sc1 + s1;
        mrow0 = mn0;
        mrow1 = mn1;
#pragma unroll
        for (int j = 0; j < 8; j++) {
            O[j][0] *= sc0; O[j][1] *= sc0;
            O[j][2] *= sc1; O[j][3] *= sc1;
        }

        // ---- P fragments (fp16 single, straight from S accumulators) ----
        uint32_t ph[4][4];
#pragma unroll
        for (int kk = 0; kk < 4; kk++) {
            ph[kk][0] = cvt2h(S[2 * kk][0],     S[2 * kk][1]);
            ph[kk][1] = cvt2h(S[2 * kk][2],     S[2 * kk][3]);
            ph[kk][2] = cvt2h(S[2 * kk + 1][0], S[2 * kk + 1][1]);
            ph[kk][3] = cvt2h(S[2 * kk + 1][2], S[2 * kk + 1][3]);
        }

        // ---- O += P V (single pass) ----
#pragma unroll
        for (int kk = 0; kk < 4; kk++) {
            uint32_t vh_[8][2];
#pragma unroll
            for (int jj = 0; jj < 4; jj++) {
                int row  = kk * 16 + rV;
                int cgrp = jj * 2 + cVb;
                uint32_t a = kvb + 8192 + row * 128 + ((cgrp ^ (row & 7)) << 4);
                LDSM_X4_T(vh_[2 * jj][0], vh_[2 * jj][1], vh_[2 * jj + 1][0], vh_[2 * jj + 1][1], a);
            }
#pragma unroll
            for (int j = 0; j < 8; j++) mma_f16(O[j], ph[kk], vh_[j]);
        }
    }

    // ---- epilogue: ctx fp16 single, layout [TB, EE] ----
    float inv0 = 1.0f / lrow0, inv1 = 1.0f / lrow1;
    int qr0 = qrow0 + m0 + g;
    int qr1 = qr0 + 8;
#pragma unroll
    for (int j = 0; j < 8; j++) {
        int col = h * 64 + 8 * j + 2 * t;
        *(uint32_t*)(g_ctx16 + (size_t)(qr0 * BB + b) * EE + col) =
            cvt2h(O[j][0] * inv0, O[j][1] * inv0);
        *(uint32_t*)(g_ctx16 + (size_t)(qr1 * BB + b) * EE + col) =
            cvt2h(O[j][2] * inv1, O[j][3] * inv1);
    }
}

// ============================================================================
// Launch
// ============================================================================
extern "C" void kernel_launch(void* const* d_in, const int* in_sizes, int n_in,
                              void* d_out, int out_size)
{
    const float* query = (const float*)d_in[0];
    const float* w_in  = (const float*)d_in[1];
    const float* b_in  = (const float*)d_in[2];
    const float* w_out = (const float*)d_in[3];
    const float* b_out = (const float*)d_in[4];
    float* out = (float*)d_out;

    __half *p_qry16, *p_wi16, *p_wo16, *p_ctx16;
    cudaGetSymbolAddress((void**)&p_qry16, g_qry16);
    cudaGetSymbolAddress((void**)&p_wi16, g_wi16);
    cudaGetSymbolAddress((void**)&p_wo16, g_wo16);
    cudaGetSymbolAddress((void**)&p_ctx16, g_ctx16);

    cudaFuncSetAttribute(mma_gemm6<0>, cudaFuncAttributeMaxDynamicSharedMemorySize, GEMM_SMEM6);
    cudaFuncSetAttribute(mma_gemm6<1>, cudaFuncAttributeMaxDynamicSharedMemorySize, GEMM_SMEM6);
    cudaFuncSetAttribute(attn_mma6, cudaFuncAttributeMaxDynamicSharedMemorySize, ATTN_SMEM6);

    // 0) converts: everything -> fp16 single
    cvt16_kernel<<<(TB * EE / 4 + 255) / 256, 256>>>(query, p_qry16, TB * EE / 4);
    cvt16_kernel<<<(FF * EE / 4 + 255) / 256, 256>>>(w_in, p_wi16, FF * EE / 4);
    cvt16_kernel<<<(EE * EE / 4 + 255) / 256, 256>>>(w_out, p_wo16, EE * EE / 4);

    // 1) QKV projection (fp16) -> q/k/v fp16 (q pre-scaled)
    mma_gemm6<0><<<dim3(FF / 128, TB / 128), 256, GEMM_SMEM6>>>(p_qry16, p_wi16, b_in, nullptr);
    // 2) Flash attention (split-group, pure fp16) -> ctx fp16
    attn_mma6<<<dim3(TQ / 128, BB * HH), 256, ATTN_SMEM6>>>();
    // 3) Output projection (fp16) -> fp32 out
    mma_gemm6<1><<<dim3(EE / 128, TB / 128), 256, GEMM_SMEM6>>>(p_ctx16, p_wo16, b_out, out);
}